// round 7
// baseline (speedup 1.0000x reference)
#include <cuda_runtime.h>
#include <cuda_bf16.h>
#include <cuda_fp8.h>
#include <cstdint>

#define NROW 4096
#define DDIM 2048
#define EPSF 1e-5f

#define BM 128
#define BN 128
#define BKB 128                 // k-bytes per chunk (= 128 fp8 elements)
#define NCHUNK (DDIM / BKB)     // 16
#define NSTAGE 3
#define TILEB (BM * 128)        // 16 KB per operand tile
#define STAGEB (2 * TILEB)      // 32 KB per stage
#define NTILE (NROW / BM)       // 32

// fp8 stores 8*x_norm; dot_true = dot_fp8 / 64 -> d = sqrt(2 - dot*2/64)
#define DOT_SCALE 0.03125f

__device__ uint8_t g_x8[NROW * DDIM];   // 8 MB normalized fp8 (x8 scale)
__device__ float g_acc[NROW * 8];
// [0]=sum pos_intra [1]=cnt pos_intra [2]=sum pos_cross [3]=cnt pos_cross
// [4]=num neg_intra [5]=den neg_intra [6]=num neg_cross [7]=den neg_cross

#define LDSM_X4(R0, R1, R2, R3, addr)                                          \
    asm volatile("ldmatrix.sync.aligned.m8n8.x4.shared.b16 {%0,%1,%2,%3}, [%4];" \
                 : "=r"(R0), "=r"(R1), "=r"(R2), "=r"(R3) : "r"(addr))

#define MMA16832(D, A, B)                                                      \
    asm volatile("mma.sync.aligned.m16n8k32.row.col.f32.e4m3.e4m3.f32 "        \
                 "{%0,%1,%2,%3},{%4,%5,%6,%7},{%8,%9},{%0,%1,%2,%3};"          \
                 : "+f"((D)[0]), "+f"((D)[1]), "+f"((D)[2]), "+f"((D)[3])      \
                 : "r"((A)[0]), "r"((A)[1]), "r"((A)[2]), "r"((A)[3]),         \
                   "r"((B)[0]), "r"((B)[1]))

__device__ __forceinline__ void cp_async16(uint32_t dst, const void* src) {
    asm volatile("cp.async.cg.shared.global [%0], [%1], 16;"
                 :: "r"(dst), "l"(src) : "memory");
}

// ---------------------------------------------------------------------------
// Kernel 1: L2-normalize rows -> fp8 g_x8 (scaled by 8); zero g_acc.
// ---------------------------------------------------------------------------
__global__ __launch_bounds__(256) void normalize_kernel(const float* __restrict__ x) {
    int row = blockIdx.x;
    int t = threadIdx.x;
    const float4* xr = (const float4*)(x + (size_t)row * DDIM);

    float4 v0 = xr[2 * t];
    float4 v1 = xr[2 * t + 1];
    float ss = v0.x * v0.x + v0.y * v0.y + v0.z * v0.z + v0.w * v0.w
             + v1.x * v1.x + v1.y * v1.y + v1.z * v1.z + v1.w * v1.w;
#pragma unroll
    for (int o = 16; o > 0; o >>= 1) ss += __shfl_xor_sync(0xffffffffu, ss, o);

    __shared__ float warpSum[8];
    __shared__ float totS;
    if ((t & 31) == 0) warpSum[t >> 5] = ss;
    __syncthreads();
    if (t == 0) {
        float tot = 0.f;
#pragma unroll
        for (int i = 0; i < 8; i++) tot += warpSum[i];
        totS = tot;
    }
    __syncthreads();

    float rinv = 8.0f / fmaxf(sqrtf(totS), 1e-12f);   // scale by 8 into fp8
    float v[8] = { v0.x, v0.y, v0.z, v0.w, v1.x, v1.y, v1.z, v1.w };
    union { uint2 u; uint8_t b[8]; } pk;
#pragma unroll
    for (int i = 0; i < 8; i++)
        pk.b[i] = (uint8_t)__nv_cvt_float_to_fp8(v[i] * rinv, __NV_SATFINITE, __NV_E4M3);
    *(uint2*)(g_x8 + (size_t)row * DDIM + 8 * t) = pk.u;

    if (t < 8) g_acc[row * 8 + t] = 0.f;
}

// ---------------------------------------------------------------------------
// Kernel 2: triangular Gram (mma.sync fp8, 3-stage cp.async) + loss epilogue.
// 256 threads = 8 warps (4 m x 2 n); warp tile 32x64.
// ---------------------------------------------------------------------------
extern __shared__ char dynsmem[];

__global__ __launch_bounds__(256) void fused_kernel(const int* __restrict__ targets,
                                                    const int* __restrict__ sub) {
    __shared__ float rowAcc[BM][8];
    __shared__ float colAcc[BN][8];
    __shared__ int tI[BM], sI[BM], tJ[BN], sJ[BN];

    // Triangular decode: blockIdx.x -> (bi, bj), bi <= bj
    int bi = 0, rem = blockIdx.x;
    while (rem >= NTILE - bi) { rem -= NTILE - bi; bi++; }
    int bj = bi + rem;
    bool diag = (bi == bj);

    int tid = threadIdx.x;
    int lane = tid & 31;
    int wid = tid >> 5;
    int warp_m = wid & 3;   // m offset 32*warp_m
    int warp_n = wid >> 2;  // n offset 64*warp_n

    uint32_t dynb = (uint32_t)__cvta_generic_to_shared(dynsmem);
    uint32_t base = (dynb + 1023u) & ~1023u;

    for (int i = tid; i < BM * 8; i += 256) {
        ((float*)rowAcc)[i] = 0.f;
        ((float*)colAcc)[i] = 0.f;
    }
    if (tid < BM) {
        tI[tid] = targets[bi * BM + tid];
        sI[tid] = sub[bi * BM + tid];
        tJ[tid] = targets[bj * BN + tid];
        sJ[tid] = sub[bj * BN + tid];
    }

    const uint8_t* Ag = g_x8 + (size_t)(bi * BM) * DDIM;
    const uint8_t* Bg = g_x8 + (size_t)(bj * BN) * DDIM;

    // Per-thread load slots: 4 x 16B per operand per stage.
    // idx = i*256 + tid -> row = idx>>3, chunk c = idx&7, phys chunk = c^(r&7).
    int lrow[4], lcoff[4], lcsw[4];
#pragma unroll
    for (int i = 0; i < 4; i++) {
        int idx = i * 256 + tid;
        lrow[i] = idx >> 3;
        int c = idx & 7;
        lcoff[i] = c * 16;                   // byte offset in gmem row
        lcsw[i] = (c ^ (lrow[i] & 7)) * 16;  // swizzled byte offset in smem row
    }

#define LOAD_STAGE(S, F)                                                           \
    do {                                                                           \
        uint32_t aB = base + (S) * STAGEB;                                         \
        uint32_t bB = aB + TILEB;                                                  \
        int k0 = (F) * BKB;                                                        \
        _Pragma("unroll")                                                          \
        for (int i = 0; i < 4; i++) {                                              \
            int r = lrow[i];                                                       \
            cp_async16(aB + r * 128 + lcsw[i], Ag + (size_t)r * DDIM + k0 + lcoff[i]); \
            cp_async16(bB + r * 128 + lcsw[i], Bg + (size_t)r * DDIM + k0 + lcoff[i]); \
        }                                                                          \
        asm volatile("cp.async.commit_group;" ::: "memory");                       \
    } while (0)

    float acc[2][8][4];
#pragma unroll
    for (int mt = 0; mt < 2; mt++)
#pragma unroll
        for (int nt = 0; nt < 8; nt++)
#pragma unroll
            for (int e = 0; e < 4; e++) acc[mt][nt][e] = 0.f;

    LOAD_STAGE(0, 0);
    LOAD_STAGE(1, 1);

    for (int c = 0; c < NCHUNK; c++) {
        if (c + 2 < NCHUNK) {
            LOAD_STAGE((c + 2) % NSTAGE, c + 2);
            asm volatile("cp.async.wait_group 2;" ::: "memory");
        } else if (c + 1 < NCHUNK) {
            asm volatile("cp.async.wait_group 1;" ::: "memory");
        } else {
            asm volatile("cp.async.wait_group 0;" ::: "memory");
        }
        __syncthreads();

        uint32_t asA = base + (c % NSTAGE) * STAGEB;
        uint32_t asB = asA + TILEB;

        // 4 k-steps of k=32 fp8 (32 bytes = 2 x 16B sub-chunks each).
#pragma unroll
        for (int ks = 0; ks < 4; ks++) {
            uint32_t a[2][4];
#pragma unroll
            for (int mt = 0; mt < 2; mt++) {
                int r = warp_m * 32 + mt * 16 + (lane & 15);
                int ce = ks * 2 + (lane >> 4);
                int cp = ce ^ (r & 7);
                LDSM_X4(a[mt][0], a[mt][1], a[mt][2], a[mt][3],
                        asA + (uint32_t)(r * 128 + cp * 16));
            }
            uint32_t b[8][2];
#pragma unroll
            for (int np = 0; np < 4; np++) {
                int r = warp_n * 64 + np * 16 + ((lane & 7) | ((lane >> 4) << 3));
                int ce = ks * 2 + ((lane >> 3) & 1);
                int cp = ce ^ (r & 7);
                LDSM_X4(b[np * 2][0], b[np * 2][1], b[np * 2 + 1][0], b[np * 2 + 1][1],
                        asB + (uint32_t)(r * 128 + cp * 16));
            }
#pragma unroll
            for (int mt = 0; mt < 2; mt++)
#pragma unroll
                for (int nt = 0; nt < 8; nt++)
                    MMA16832(acc[mt][nt], a[mt], b[nt]);
        }
        __syncthreads();
    }

    // Convert scaled dots -> distances in place.
#pragma unroll
    for (int mt = 0; mt < 2; mt++)
#pragma unroll
        for (int nt = 0; nt < 8; nt++)
#pragma unroll
            for (int e = 0; e < 4; e++)
                acc[mt][nt][e] = sqrtf(fmaxf(2.f - acc[mt][nt][e] * DOT_SCALE, 1e-12f));

    // Fragment layout: row = warp_m*32 + mt*16 + (e>>1)*8 + lane/4
    //                  col = warp_n*64 + nt*8 + (lane&3)*2 + (e&1)

    // ---- Row pass ----
#pragma unroll
    for (int mt = 0; mt < 2; mt++) {
#pragma unroll
        for (int h = 0; h < 2; h++) {
            int li = warp_m * 32 + mt * 16 + h * 8 + (lane >> 2);
            int gi = bi * BM + li;
            int ti = tI[li], si = sI[li];
            float p0 = 0.f, p1 = 0.f, p2 = 0.f, p3 = 0.f;
            float p4 = 0.f, p5 = 0.f, p6 = 0.f, p7 = 0.f;
#pragma unroll
            for (int nt = 0; nt < 8; nt++) {
#pragma unroll
                for (int cc = 0; cc < 2; cc++) {
                    int lj = warp_n * 64 + nt * 8 + (lane & 3) * 2 + cc;
                    int gj = bj * BN + lj;
                    float d = acc[mt][nt][h * 2 + cc];
                    bool same = (ti == tJ[lj]);
                    bool intra = (si == sJ[lj]);
                    if (same) {
                        if (gi != gj) {
                            if (intra) { p0 += fmaxf(d - 1.4f, 0.f); p1 += 1.f; }
                            else       { p2 += fmaxf(d - 0.7f, 0.f); p3 += 1.f; }
                        }
                    } else {
                        float alpha = intra ? 2.4f : 2.2f;
                        if (d < alpha) {
                            float diff = alpha - d;
                            float w = __expf(diff);
                            if (intra) { p4 += diff * w; p5 += w; }
                            else       { p6 += diff * w; p7 += w; }
                        }
                    }
                }
            }
#pragma unroll
            for (int o = 1; o <= 2; o <<= 1) {
                p0 += __shfl_xor_sync(0xffffffffu, p0, o);
                p1 += __shfl_xor_sync(0xffffffffu, p1, o);
                p2 += __shfl_xor_sync(0xffffffffu, p2, o);
                p3 += __shfl_xor_sync(0xffffffffu, p3, o);
                p4 += __shfl_xor_sync(0xffffffffu, p4, o);
                p5 += __shfl_xor_sync(0xffffffffu, p5, o);
                p6 += __shfl_xor_sync(0xffffffffu, p6, o);
                p7 += __shfl_xor_sync(0xffffffffu, p7, o);
            }
            if ((lane & 3) == 0) {
                if (p1 != 0.f) { atomicAdd(&rowAcc[li][0], p0); atomicAdd(&rowAcc[li][1], p1); }
                if (p3 != 0.f) { atomicAdd(&rowAcc[li][2], p2); atomicAdd(&rowAcc[li][3], p3); }
                if (p5 != 0.f) { atomicAdd(&rowAcc[li][4], p4); atomicAdd(&rowAcc[li][5], p5); }
                if (p7 != 0.f) { atomicAdd(&rowAcc[li][6], p6); atomicAdd(&rowAcc[li][7], p7); }
            }
        }
    }

    // ---- Column pass (symmetry credit), off-diagonal only ----
    if (!diag) {
#pragma unroll
        for (int nt = 0; nt < 8; nt++) {
#pragma unroll
            for (int cc = 0; cc < 2; cc++) {
                int lj = warp_n * 64 + nt * 8 + (lane & 3) * 2 + cc;
                int tj = tJ[lj], sj = sJ[lj];
                float p0 = 0.f, p1 = 0.f, p2 = 0.f, p3 = 0.f;
                float p4 = 0.f, p5 = 0.f, p6 = 0.f, p7 = 0.f;
#pragma unroll
                for (int mt = 0; mt < 2; mt++) {
#pragma unroll
                    for (int h = 0; h < 2; h++) {
                        int li = warp_m * 32 + mt * 16 + h * 8 + (lane >> 2);
                        float d = acc[mt][nt][h * 2 + cc];
                        bool same = (tI[li] == tj);
                        bool intra = (sI[li] == sj);
                        if (same) {
                            if (intra) { p0 += fmaxf(d - 1.4f, 0.f); p1 += 1.f; }
                            else       { p2 += fmaxf(d - 0.7f, 0.f); p3 += 1.f; }
                        } else {
                            float alpha = intra ? 2.4f : 2.2f;
                            if (d < alpha) {
                                float diff = alpha - d;
                                float w = __expf(diff);
                                if (intra) { p4 += diff * w; p5 += w; }
                                else       { p6 += diff * w; p7 += w; }
                            }
                        }
                    }
                }
#pragma unroll
                for (int o = 4; o <= 16; o <<= 1) {
                    p0 += __shfl_xor_sync(0xffffffffu, p0, o);
                    p1 += __shfl_xor_sync(0xffffffffu, p1, o);
                    p2 += __shfl_xor_sync(0xffffffffu, p2, o);
                    p3 += __shfl_xor_sync(0xffffffffu, p3, o);
                    p4 += __shfl_xor_sync(0xffffffffu, p4, o);
                    p5 += __shfl_xor_sync(0xffffffffu, p5, o);
                    p6 += __shfl_xor_sync(0xffffffffu, p6, o);
                    p7 += __shfl_xor_sync(0xffffffffu, p7, o);
                }
                if (lane < 4) {
                    if (p1 != 0.f) { atomicAdd(&colAcc[lj][0], p0); atomicAdd(&colAcc[lj][1], p1); }
                    if (p3 != 0.f) { atomicAdd(&colAcc[lj][2], p2); atomicAdd(&colAcc[lj][3], p3); }
                    if (p5 != 0.f) { atomicAdd(&colAcc[lj][4], p4); atomicAdd(&colAcc[lj][5], p5); }
                    if (p7 != 0.f) { atomicAdd(&colAcc[lj][6], p6); atomicAdd(&colAcc[lj][7], p7); }
                }
            }
        }
    }

    __syncthreads();

    for (int i = tid; i < BM * 8; i += 256) {
        int r = i >> 3, s = i & 7;
        float v = ((float*)rowAcc)[i];
        if (v != 0.f) atomicAdd(&g_acc[(bi * BM + r) * 8 + s], v);
        if (!diag) {
            float vc = ((float*)colAcc)[i];
            if (vc != 0.f) atomicAdd(&g_acc[(bj * BN + r) * 8 + s], vc);
        }
    }
}

// ---------------------------------------------------------------------------
// Kernel 3: finalize.
// ---------------------------------------------------------------------------
__global__ __launch_bounds__(256) void finalize_kernel(float* __restrict__ out) {
    int t = threadIdx.x;
    float s = 0.f;
    for (int r = t; r < NROW; r += 256) {
        const float* a = g_acc + r * 8;
        s += a[0] / (a[1] + EPSF) + a[2] / (a[3] + EPSF)
           + a[4] / (a[5] + EPSF) + a[6] / (a[7] + EPSF);
    }
#pragma unroll
    for (int o = 16; o > 0; o >>= 1) s += __shfl_xor_sync(0xffffffffu, s, o);
    __shared__ float ws[8];
    if ((t & 31) == 0) ws[t >> 5] = s;
    __syncthreads();
    if (t == 0) {
        float tot = 0.f;
#pragma unroll
        for (int i = 0; i < 8; i++) tot += ws[i];
        out[0] = tot / (float)NROW;
    }
}

extern "C" void kernel_launch(void* const* d_in, const int* in_sizes, int n_in,
                              void* d_out, int out_size) {
    const float* x       = (const float*)d_in[0];
    const int*   targets = (const int*)d_in[1];
    const int*   sub     = (const int*)d_in[2];

    int dyn = 1024 + NSTAGE * STAGEB;  // 97.3 KB
    cudaFuncSetAttribute(fused_kernel, cudaFuncAttributeMaxDynamicSharedMemorySize, dyn);

    normalize_kernel<<<NROW, 256>>>(x);
    fused_kernel<<<(NTILE * (NTILE + 1)) / 2, 256, dyn>>>(targets, sub);
    finalize_kernel<<<1, 256>>>((float*)d_out);
}

// round 8
// speedup vs baseline: 1.1128x; 1.1128x over previous
#include <cuda_runtime.h>
#include <cuda_bf16.h>
#include <cstdint>

#define NROW 4096
#define DDIM 2048
#define EPSF 1e-5f

#define BM 128
#define BN 128
#define BKH 64                  // halves per k-chunk (128 bytes/row)
#define NCHUNK (DDIM / BKH)     // 32
#define NSTAGE 3
#define TILEB (BM * 128)        // 16 KB per operand tile
#define STAGEB (2 * TILEB)      // 32 KB per stage
#define NTILE (NROW / BM)       // 32

__device__ __nv_bfloat16 g_xb[NROW * DDIM];   // 16 MB normalized bf16
__device__ float g_acc[NROW * 8];
// [0]=sum pos_intra [1]=cnt pos_intra [2]=sum pos_cross [3]=cnt pos_cross
// [4]=num neg_intra [5]=den neg_intra [6]=num neg_cross [7]=den neg_cross

#define LDSM_X4(R0, R1, R2, R3, addr)                                          \
    asm volatile("ldmatrix.sync.aligned.m8n8.x4.shared.b16 {%0,%1,%2,%3}, [%4];" \
                 : "=r"(R0), "=r"(R1), "=r"(R2), "=r"(R3) : "r"(addr))

#define MMA16816(D, A, B)                                                      \
    asm volatile("mma.sync.aligned.m16n8k16.row.col.f32.bf16.bf16.f32 "        \
                 "{%0,%1,%2,%3},{%4,%5,%6,%7},{%8,%9},{%0,%1,%2,%3};"          \
                 : "+f"((D)[0]), "+f"((D)[1]), "+f"((D)[2]), "+f"((D)[3])      \
                 : "r"((A)[0]), "r"((A)[1]), "r"((A)[2]), "r"((A)[3]),         \
                   "r"((B)[0]), "r"((B)[1]))

__device__ __forceinline__ void cp_async16(uint32_t dst, const void* src) {
    asm volatile("cp.async.cg.shared.global [%0], [%1], 16;"
                 :: "r"(dst), "l"(src) : "memory");
}

// ---------------------------------------------------------------------------
// Kernel 1: L2-normalize rows -> bf16 g_xb; zero g_acc.
// ---------------------------------------------------------------------------
__global__ __launch_bounds__(256) void normalize_kernel(const float* __restrict__ x) {
    int row = blockIdx.x;
    int t = threadIdx.x;
    const float4* xr = (const float4*)(x + (size_t)row * DDIM);

    float4 v0 = xr[2 * t];
    float4 v1 = xr[2 * t + 1];
    float ss = v0.x * v0.x + v0.y * v0.y + v0.z * v0.z + v0.w * v0.w
             + v1.x * v1.x + v1.y * v1.y + v1.z * v1.z + v1.w * v1.w;
#pragma unroll
    for (int o = 16; o > 0; o >>= 1) ss += __shfl_xor_sync(0xffffffffu, ss, o);

    __shared__ float warpSum[8];
    __shared__ float totS;
    if ((t & 31) == 0) warpSum[t >> 5] = ss;
    __syncthreads();
    if (t == 0) {
        float tot = 0.f;
#pragma unroll
        for (int i = 0; i < 8; i++) tot += warpSum[i];
        totS = tot;
    }
    __syncthreads();

    float rinv = 1.0f / fmaxf(sqrtf(totS), 1e-12f);
    union { uint4 u; __nv_bfloat162 h[4]; } pk;
    pk.h[0] = __floats2bfloat162_rn(v0.x * rinv, v0.y * rinv);
    pk.h[1] = __floats2bfloat162_rn(v0.z * rinv, v0.w * rinv);
    pk.h[2] = __floats2bfloat162_rn(v1.x * rinv, v1.y * rinv);
    pk.h[3] = __floats2bfloat162_rn(v1.z * rinv, v1.w * rinv);
    *(uint4*)(g_xb + (size_t)row * DDIM + 8 * t) = pk.u;

    if (t < 8) g_acc[row * 8 + t] = 0.f;
}

// ---------------------------------------------------------------------------
// Kernel 2: triangular Gram (mma.sync bf16, 3-stage cp.async) + loss epilogue.
// 128 threads = 4 warps in 2x2 grid; warp tile 64x64.
// ---------------------------------------------------------------------------
extern __shared__ char dynsmem[];

__global__ __launch_bounds__(128) void fused_kernel(const int* __restrict__ targets,
                                                    const int* __restrict__ sub) {
    __shared__ float rowAcc[BM][8];
    __shared__ float colAcc[BN][8];
    __shared__ int tI[BM], sI[BM], tJ[BN], sJ[BN];

    // Triangular decode: blockIdx.x -> (bi, bj), bi <= bj
    int bi = 0, rem = blockIdx.x;
    while (rem >= NTILE - bi) { rem -= NTILE - bi; bi++; }
    int bj = bi + rem;
    bool diag = (bi == bj);

    int tid = threadIdx.x;
    int lane = tid & 31;
    int wid = tid >> 5;
    int warp_m = wid & 1;   // m offset 64*warp_m
    int warp_n = wid >> 1;  // n offset 64*warp_n

    uint32_t dynb = (uint32_t)__cvta_generic_to_shared(dynsmem);
    uint32_t base = (dynb + 1023u) & ~1023u;

    for (int i = tid; i < BM * 8; i += 128) {
        ((float*)rowAcc)[i] = 0.f;
        ((float*)colAcc)[i] = 0.f;
    }
    {
        tI[tid] = targets[bi * BM + tid];
        sI[tid] = sub[bi * BM + tid];
        tJ[tid] = targets[bj * BN + tid];
        sJ[tid] = sub[bj * BN + tid];
    }

    const __nv_bfloat16* Ag = g_xb + (size_t)(bi * BM) * DDIM;
    const __nv_bfloat16* Bg = g_xb + (size_t)(bj * BN) * DDIM;

    // Per-thread load slots: 8 x 16B per operand per stage.
    // idx = i*128 + tid -> row = idx>>3, chunk c = idx&7, phys chunk = c^(r&7).
    int lrow[8], lcoff[8], lcsw[8];
#pragma unroll
    for (int i = 0; i < 8; i++) {
        int idx = i * 128 + tid;
        lrow[i] = idx >> 3;
        int c = idx & 7;
        lcoff[i] = c * 8;                    // halves offset in gmem row
        lcsw[i] = (c ^ (lrow[i] & 7)) * 16;  // swizzled byte offset in smem row
    }

#define LOAD_STAGE(S, F)                                                           \
    do {                                                                           \
        uint32_t aB = base + (S) * STAGEB;                                         \
        uint32_t bB = aB + TILEB;                                                  \
        int k0 = (F) * BKH;                                                        \
        _Pragma("unroll")                                                          \
        for (int i = 0; i < 8; i++) {                                              \
            int r = lrow[i];                                                       \
            cp_async16(aB + r * 128 + lcsw[i], Ag + (size_t)r * DDIM + k0 + lcoff[i]); \
            cp_async16(bB + r * 128 + lcsw[i], Bg + (size_t)r * DDIM + k0 + lcoff[i]); \
        }                                                                          \
        asm volatile("cp.async.commit_group;" ::: "memory");                       \
    } while (0)

    float acc[4][8][4];
#pragma unroll
    for (int mt = 0; mt < 4; mt++)
#pragma unroll
        for (int nt = 0; nt < 8; nt++)
#pragma unroll
            for (int e = 0; e < 4; e++) acc[mt][nt][e] = 0.f;

    LOAD_STAGE(0, 0);
    LOAD_STAGE(1, 1);

    for (int c = 0; c < NCHUNK; c++) {
        if (c + 2 < NCHUNK) {
            LOAD_STAGE((c + 2) % NSTAGE, c + 2);
            asm volatile("cp.async.wait_group 2;" ::: "memory");
        } else if (c + 1 < NCHUNK) {
            asm volatile("cp.async.wait_group 1;" ::: "memory");
        } else {
            asm volatile("cp.async.wait_group 0;" ::: "memory");
        }
        __syncthreads();

        uint32_t asA = base + (c % NSTAGE) * STAGEB;
        uint32_t asB = asA + TILEB;

#pragma unroll
        for (int ks = 0; ks < 4; ks++) {
            uint32_t a[4][4];
#pragma unroll
            for (int mt = 0; mt < 4; mt++) {
                int r = warp_m * 64 + mt * 16 + (lane & 15);
                int ce = ks * 2 + (lane >> 4);
                int cp = ce ^ (r & 7);
                LDSM_X4(a[mt][0], a[mt][1], a[mt][2], a[mt][3],
                        asA + (uint32_t)(r * 128 + cp * 16));
            }
            uint32_t b[8][2];
#pragma unroll
            for (int np = 0; np < 4; np++) {
                int r = warp_n * 64 + np * 16 + ((lane & 7) | ((lane >> 4) << 3));
                int ce = ks * 2 + ((lane >> 3) & 1);
                int cp = ce ^ (r & 7);
                LDSM_X4(b[np * 2][0], b[np * 2][1], b[np * 2 + 1][0], b[np * 2 + 1][1],
                        asB + (uint32_t)(r * 128 + cp * 16));
            }
#pragma unroll
            for (int mt = 0; mt < 4; mt++)
#pragma unroll
                for (int nt = 0; nt < 8; nt++)
                    MMA16816(acc[mt][nt], a[mt], b[nt]);
        }
        __syncthreads();
    }

    // Convert dots -> distances in place.
#pragma unroll
    for (int mt = 0; mt < 4; mt++)
#pragma unroll
        for (int nt = 0; nt < 8; nt++)
#pragma unroll
            for (int e = 0; e < 4; e++)
                acc[mt][nt][e] = sqrtf(fmaxf(2.f - 2.f * acc[mt][nt][e], 1e-12f));

    // Fragment layout: row = warp_m*64 + mt*16 + (e>>1)*8 + lane/4
    //                  col = warp_n*64 + nt*8 + (lane&3)*2 + (e&1)

    // ---- Row pass ----
#pragma unroll
    for (int mt = 0; mt < 4; mt++) {
#pragma unroll
        for (int h = 0; h < 2; h++) {
            int li = warp_m * 64 + mt * 16 + h * 8 + (lane >> 2);
            int gi = bi * BM + li;
            int ti = tI[li], si = sI[li];
            float p0 = 0.f, p1 = 0.f, p2 = 0.f, p3 = 0.f;
            float p4 = 0.f, p5 = 0.f, p6 = 0.f, p7 = 0.f;
#pragma unroll
            for (int nt = 0; nt < 8; nt++) {
#pragma unroll
                for (int cc = 0; cc < 2; cc++) {
                    int lj = warp_n * 64 + nt * 8 + (lane & 3) * 2 + cc;
                    int gj = bj * BN + lj;
                    float d = acc[mt][nt][h * 2 + cc];
                    bool same = (ti == tJ[lj]);
                    bool intra = (si == sJ[lj]);
                    if (same) {
                        if (gi != gj) {
                            if (intra) { p0 += fmaxf(d - 1.4f, 0.f); p1 += 1.f; }
                            else       { p2 += fmaxf(d - 0.7f, 0.f); p3 += 1.f; }
                        }
                    } else {
                        float alpha = intra ? 2.4f : 2.2f;
                        if (d < alpha) {
                            float diff = alpha - d;
                            float w = __expf(diff);
                            if (intra) { p4 += diff * w; p5 += w; }
                            else       { p6 += diff * w; p7 += w; }
                        }
                    }
                }
            }
#pragma unroll
            for (int o = 1; o <= 2; o <<= 1) {
                p0 += __shfl_xor_sync(0xffffffffu, p0, o);
                p1 += __shfl_xor_sync(0xffffffffu, p1, o);
                p2 += __shfl_xor_sync(0xffffffffu, p2, o);
                p3 += __shfl_xor_sync(0xffffffffu, p3, o);
                p4 += __shfl_xor_sync(0xffffffffu, p4, o);
                p5 += __shfl_xor_sync(0xffffffffu, p5, o);
                p6 += __shfl_xor_sync(0xffffffffu, p6, o);
                p7 += __shfl_xor_sync(0xffffffffu, p7, o);
            }
            if ((lane & 3) == 0) {
                if (p1 != 0.f) { atomicAdd(&rowAcc[li][0], p0); atomicAdd(&rowAcc[li][1], p1); }
                if (p3 != 0.f) { atomicAdd(&rowAcc[li][2], p2); atomicAdd(&rowAcc[li][3], p3); }
                if (p5 != 0.f) { atomicAdd(&rowAcc[li][4], p4); atomicAdd(&rowAcc[li][5], p5); }
                if (p7 != 0.f) { atomicAdd(&rowAcc[li][6], p6); atomicAdd(&rowAcc[li][7], p7); }
            }
        }
    }

    // ---- Column pass (symmetry credit), off-diagonal only ----
    if (!diag) {
#pragma unroll
        for (int nt = 0; nt < 8; nt++) {
#pragma unroll
            for (int cc = 0; cc < 2; cc++) {
                int lj = warp_n * 64 + nt * 8 + (lane & 3) * 2 + cc;
                int tj = tJ[lj], sj = sJ[lj];
                float p0 = 0.f, p1 = 0.f, p2 = 0.f, p3 = 0.f;
                float p4 = 0.f, p5 = 0.f, p6 = 0.f, p7 = 0.f;
#pragma unroll
                for (int mt = 0; mt < 4; mt++) {
#pragma unroll
                    for (int h = 0; h < 2; h++) {
                        int li = warp_m * 64 + mt * 16 + h * 8 + (lane >> 2);
                        float d = acc[mt][nt][h * 2 + cc];
                        bool same = (tI[li] == tj);
                        bool intra = (sI[li] == sj);
                        if (same) {
                            if (intra) { p0 += fmaxf(d - 1.4f, 0.f); p1 += 1.f; }
                            else       { p2 += fmaxf(d - 0.7f, 0.f); p3 += 1.f; }
                        } else {
                            float alpha = intra ? 2.4f : 2.2f;
                            if (d < alpha) {
                                float diff = alpha - d;
                                float w = __expf(diff);
                                if (intra) { p4 += diff * w; p5 += w; }
                                else       { p6 += diff * w; p7 += w; }
                            }
                        }
                    }
                }
#pragma unroll
                for (int o = 4; o <= 16; o <<= 1) {
                    p0 += __shfl_xor_sync(0xffffffffu, p0, o);
                    p1 += __shfl_xor_sync(0xffffffffu, p1, o);
                    p2 += __shfl_xor_sync(0xffffffffu, p2, o);
                    p3 += __shfl_xor_sync(0xffffffffu, p3, o);
                    p4 += __shfl_xor_sync(0xffffffffu, p4, o);
                    p5 += __shfl_xor_sync(0xffffffffu, p5, o);
                    p6 += __shfl_xor_sync(0xffffffffu, p6, o);
                    p7 += __shfl_xor_sync(0xffffffffu, p7, o);
                }
                if (lane < 4) {
                    if (p1 != 0.f) { atomicAdd(&colAcc[lj][0], p0); atomicAdd(&colAcc[lj][1], p1); }
                    if (p3 != 0.f) { atomicAdd(&colAcc[lj][2], p2); atomicAdd(&colAcc[lj][3], p3); }
                    if (p5 != 0.f) { atomicAdd(&colAcc[lj][4], p4); atomicAdd(&colAcc[lj][5], p5); }
                    if (p7 != 0.f) { atomicAdd(&colAcc[lj][6], p6); atomicAdd(&colAcc[lj][7], p7); }
                }
            }
        }
    }

    __syncthreads();

    for (int i = tid; i < BM * 8; i += 128) {
        int r = i >> 3, s = i & 7;
        float v = ((float*)rowAcc)[i];
        if (v != 0.f) atomicAdd(&g_acc[(bi * BM + r) * 8 + s], v);
        if (!diag) {
            float vc = ((float*)colAcc)[i];
            if (vc != 0.f) atomicAdd(&g_acc[(bj * BN + r) * 8 + s], vc);
        }
    }
}

// ---------------------------------------------------------------------------
// Kernel 3: finalize.
// ---------------------------------------------------------------------------
__global__ __launch_bounds__(256) void finalize_kernel(float* __restrict__ out) {
    int t = threadIdx.x;
    float s = 0.f;
    for (int r = t; r < NROW; r += 256) {
        const float* a = g_acc + r * 8;
        s += a[0] / (a[1] + EPSF) + a[2] / (a[3] + EPSF)
           + a[4] / (a[5] + EPSF) + a[6] / (a[7] + EPSF);
    }
#pragma unroll
    for (int o = 16; o > 0; o >>= 1) s += __shfl_xor_sync(0xffffffffu, s, o);
    __shared__ float ws[8];
    if ((t & 31) == 0) ws[t >> 5] = s;
    __syncthreads();
    if (t == 0) {
        float tot = 0.f;
#pragma unroll
        for (int i = 0; i < 8; i++) tot += ws[i];
        out[0] = tot / (float)NROW;
    }
}

extern "C" void kernel_launch(void* const* d_in, const int* in_sizes, int n_in,
                              void* d_out, int out_size) {
    const float* x       = (const float*)d_in[0];
    const int*   targets = (const int*)d_in[1];
    const int*   sub     = (const int*)d_in[2];

    int dyn = 1024 + NSTAGE * STAGEB;  // 97.3 KB
    cudaFuncSetAttribute(fused_kernel, cudaFuncAttributeMaxDynamicSharedMemorySize, dyn);

    normalize_kernel<<<NROW, 256>>>(x);
    fused_kernel<<<(NTILE * (NTILE + 1)) / 2, 128, dyn>>>(targets, sub);
    finalize_kernel<<<1, 256>>>((float*)d_out);
}

// round 9
// speedup vs baseline: 1.4437x; 1.2974x over previous
#include <cuda_runtime.h>
#include <cuda_bf16.h>
#include <cstdint>

#define NROW 4096
#define DDIM 2048
#define EPSF 1e-5f

#define BM 128
#define BN 128
#define BKH 64                  // halves per k-chunk (128 bytes/row)
#define NCHUNK (DDIM / BKH)     // 32
#define NSTAGE 3
#define TILEB (BM * 128)        // 16 KB per operand tile
#define STAGEB (2 * TILEB)      // 32 KB per stage
#define NTILE (NROW / BM)       // 32

__device__ __nv_bfloat16 g_xb[NROW * DDIM];   // 16 MB normalized bf16
__device__ float g_acc[NROW * 8];
// [0]=sum pos_intra [1]=cnt pos_intra [2]=sum pos_cross [3]=cnt pos_cross
// [4]=num neg_intra [5]=den neg_intra [6]=num neg_cross [7]=den neg_cross

#define LDSM_X4(R0, R1, R2, R3, addr)                                          \
    asm volatile("ldmatrix.sync.aligned.m8n8.x4.shared.b16 {%0,%1,%2,%3}, [%4];" \
                 : "=r"(R0), "=r"(R1), "=r"(R2), "=r"(R3) : "r"(addr))

#define MMA16816(D, A, B)                                                      \
    asm volatile("mma.sync.aligned.m16n8k16.row.col.f32.bf16.bf16.f32 "        \
                 "{%0,%1,%2,%3},{%4,%5,%6,%7},{%8,%9},{%0,%1,%2,%3};"          \
                 : "+f"((D)[0]), "+f"((D)[1]), "+f"((D)[2]), "+f"((D)[3])      \
                 : "r"((A)[0]), "r"((A)[1]), "r"((A)[2]), "r"((A)[3]),         \
                   "r"((B)[0]), "r"((B)[1]))

__device__ __forceinline__ void cp_async16(uint32_t dst, const void* src) {
    asm volatile("cp.async.cg.shared.global [%0], [%1], 16;"
                 :: "r"(dst), "l"(src) : "memory");
}

// ---------------------------------------------------------------------------
// Kernel 1: L2-normalize rows -> bf16 g_xb; zero g_acc.
// ---------------------------------------------------------------------------
__global__ __launch_bounds__(256) void normalize_kernel(const float* __restrict__ x) {
    int row = blockIdx.x;
    int t = threadIdx.x;
    const float4* xr = (const float4*)(x + (size_t)row * DDIM);

    float4 v0 = xr[2 * t];
    float4 v1 = xr[2 * t + 1];
    float ss = v0.x * v0.x + v0.y * v0.y + v0.z * v0.z + v0.w * v0.w
             + v1.x * v1.x + v1.y * v1.y + v1.z * v1.z + v1.w * v1.w;
#pragma unroll
    for (int o = 16; o > 0; o >>= 1) ss += __shfl_xor_sync(0xffffffffu, ss, o);

    __shared__ float warpSum[8];
    __shared__ float totS;
    if ((t & 31) == 0) warpSum[t >> 5] = ss;
    __syncthreads();
    if (t == 0) {
        float tot = 0.f;
#pragma unroll
        for (int i = 0; i < 8; i++) tot += warpSum[i];
        totS = tot;
    }
    __syncthreads();

    float rinv = 1.0f / fmaxf(sqrtf(totS), 1e-12f);
    union { uint4 u; __nv_bfloat162 h[4]; } pk;
    pk.h[0] = __floats2bfloat162_rn(v0.x * rinv, v0.y * rinv);
    pk.h[1] = __floats2bfloat162_rn(v0.z * rinv, v0.w * rinv);
    pk.h[2] = __floats2bfloat162_rn(v1.x * rinv, v1.y * rinv);
    pk.h[3] = __floats2bfloat162_rn(v1.z * rinv, v1.w * rinv);
    *(uint4*)(g_xb + (size_t)row * DDIM + 8 * t) = pk.u;

    if (t < 8) g_acc[row * 8 + t] = 0.f;
}

// ---------------------------------------------------------------------------
// Kernel 2: triangular Gram (mma.sync bf16, 3-stage cp.async, single barrier
// per chunk) + loss epilogue. 256 threads = 8 warps (4 m x 2 n), tile 32x64.
// ---------------------------------------------------------------------------
extern __shared__ char dynsmem[];

__global__ __launch_bounds__(256, 2) void fused_kernel(const int* __restrict__ targets,
                                                       const int* __restrict__ sub) {
    __shared__ float rowAcc[BM][8];
    __shared__ float colAcc[BN][8];
    __shared__ int tI[BM], sI[BM], tJ[BN], sJ[BN];

    // Triangular decode: blockIdx.x -> (bi, bj), bi <= bj
    int bi = 0, rem = blockIdx.x;
    while (rem >= NTILE - bi) { rem -= NTILE - bi; bi++; }
    int bj = bi + rem;
    bool diag = (bi == bj);

    int tid = threadIdx.x;
    int lane = tid & 31;
    int wid = tid >> 5;
    int warp_m = wid & 3;   // m offset 32*warp_m
    int warp_n = wid >> 2;  // n offset 64*warp_n

    uint32_t dynb = (uint32_t)__cvta_generic_to_shared(dynsmem);
    uint32_t base = (dynb + 1023u) & ~1023u;

    for (int i = tid; i < BM * 8; i += 256) {
        ((float*)rowAcc)[i] = 0.f;
        ((float*)colAcc)[i] = 0.f;
    }
    if (tid < BM) {
        tI[tid] = targets[bi * BM + tid];
        sI[tid] = sub[bi * BM + tid];
        tJ[tid] = targets[bj * BN + tid];
        sJ[tid] = sub[bj * BN + tid];
    }

    const __nv_bfloat16* Ag = g_xb + (size_t)(bi * BM) * DDIM;
    const __nv_bfloat16* Bg = g_xb + (size_t)(bj * BN) * DDIM;

    // Per-thread load slots: 4 x 16B per operand per stage.
    // idx = i*256 + tid -> row = idx>>3, chunk c = idx&7, phys chunk = c^(r&7).
    int lrow[4], lcoff[4], lcsw[4];
#pragma unroll
    for (int i = 0; i < 4; i++) {
        int idx = i * 256 + tid;
        lrow[i] = idx >> 3;
        int c = idx & 7;
        lcoff[i] = c * 8;                    // halves offset in gmem row
        lcsw[i] = (c ^ (lrow[i] & 7)) * 16;  // swizzled byte offset in smem row
    }

#define LOAD_STAGE(S, F)                                                           \
    do {                                                                           \
        uint32_t aB = base + (S) * STAGEB;                                         \
        uint32_t bB = aB + TILEB;                                                  \
        int k0 = (F) * BKH;                                                        \
        _Pragma("unroll")                                                          \
        for (int i = 0; i < 4; i++) {                                              \
            int r = lrow[i];                                                       \
            cp_async16(aB + r * 128 + lcsw[i], Ag + (size_t)r * DDIM + k0 + lcoff[i]); \
            cp_async16(bB + r * 128 + lcsw[i], Bg + (size_t)r * DDIM + k0 + lcoff[i]); \
        }                                                                          \
        asm volatile("cp.async.commit_group;" ::: "memory");                       \
    } while (0)

    float acc[2][8][4];
#pragma unroll
    for (int mt = 0; mt < 2; mt++)
#pragma unroll
        for (int nt = 0; nt < 8; nt++)
#pragma unroll
            for (int e = 0; e < 4; e++) acc[mt][nt][e] = 0.f;

    LOAD_STAGE(0, 0);
    LOAD_STAGE(1, 1);

    // Single-barrier mainloop. At the top barrier of chunk c, all warps have
    // finished compute(c-1), so stage (c-1)%3 — the destination of LOAD(c+2)
    // — is free. In flight at the wait: groups {c, c+1} -> wait_group 1.
    for (int c = 0; c < NCHUNK; c++) {
        if (c + 1 < NCHUNK)
            asm volatile("cp.async.wait_group 1;" ::: "memory");
        else
            asm volatile("cp.async.wait_group 0;" ::: "memory");
        __syncthreads();
        if (c + 2 < NCHUNK) LOAD_STAGE((c + 2) % NSTAGE, c + 2);

        uint32_t asA = base + (c % NSTAGE) * STAGEB;
        uint32_t asB = asA + TILEB;

#pragma unroll
        for (int ks = 0; ks < 4; ks++) {
            uint32_t a[2][4];
#pragma unroll
            for (int mt = 0; mt < 2; mt++) {
                int r = warp_m * 32 + mt * 16 + (lane & 15);
                int ce = ks * 2 + (lane >> 4);
                int cp = ce ^ (r & 7);
                LDSM_X4(a[mt][0], a[mt][1], a[mt][2], a[mt][3],
                        asA + (uint32_t)(r * 128 + cp * 16));
            }
            uint32_t b[8][2];
#pragma unroll
            for (int np = 0; np < 4; np++) {
                int r = warp_n * 64 + np * 16 + ((lane & 7) | ((lane >> 4) << 3));
                int ce = ks * 2 + ((lane >> 3) & 1);
                int cp = ce ^ (r & 7);
                LDSM_X4(b[np * 2][0], b[np * 2][1], b[np * 2 + 1][0], b[np * 2 + 1][1],
                        asB + (uint32_t)(r * 128 + cp * 16));
            }
#pragma unroll
            for (int mt = 0; mt < 2; mt++)
#pragma unroll
                for (int nt = 0; nt < 8; nt++)
                    MMA16816(acc[mt][nt], a[mt], b[nt]);
        }
    }

    // Convert dots -> distances in place.
#pragma unroll
    for (int mt = 0; mt < 2; mt++)
#pragma unroll
        for (int nt = 0; nt < 8; nt++)
#pragma unroll
            for (int e = 0; e < 4; e++)
                acc[mt][nt][e] = sqrtf(fmaxf(2.f - 2.f * acc[mt][nt][e], 1e-12f));

    // Fragment layout: row = warp_m*32 + mt*16 + (e>>1)*8 + lane/4
    //                  col = warp_n*64 + nt*8 + (lane&3)*2 + (e&1)

    // ---- Row pass ----
#pragma unroll
    for (int mt = 0; mt < 2; mt++) {
#pragma unroll
        for (int h = 0; h < 2; h++) {
            int li = warp_m * 32 + mt * 16 + h * 8 + (lane >> 2);
            int gi = bi * BM + li;
            int ti = tI[li], si = sI[li];
            float p0 = 0.f, p1 = 0.f, p2 = 0.f, p3 = 0.f;
            float p4 = 0.f, p5 = 0.f, p6 = 0.f, p7 = 0.f;
#pragma unroll
            for (int nt = 0; nt < 8; nt++) {
#pragma unroll
                for (int cc = 0; cc < 2; cc++) {
                    int lj = warp_n * 64 + nt * 8 + (lane & 3) * 2 + cc;
                    int gj = bj * BN + lj;
                    float d = acc[mt][nt][h * 2 + cc];
                    bool same = (ti == tJ[lj]);
                    bool intra = (si == sJ[lj]);
                    if (same) {
                        if (gi != gj) {
                            if (intra) { p0 += fmaxf(d - 1.4f, 0.f); p1 += 1.f; }
                            else       { p2 += fmaxf(d - 0.7f, 0.f); p3 += 1.f; }
                        }
                    } else {
                        float alpha = intra ? 2.4f : 2.2f;
                        if (d < alpha) {
                            float diff = alpha - d;
                            float w = __expf(diff);
                            if (intra) { p4 += diff * w; p5 += w; }
                            else       { p6 += diff * w; p7 += w; }
                        }
                    }
                }
            }
#pragma unroll
            for (int o = 1; o <= 2; o <<= 1) {
                p0 += __shfl_xor_sync(0xffffffffu, p0, o);
                p1 += __shfl_xor_sync(0xffffffffu, p1, o);
                p2 += __shfl_xor_sync(0xffffffffu, p2, o);
                p3 += __shfl_xor_sync(0xffffffffu, p3, o);
                p4 += __shfl_xor_sync(0xffffffffu, p4, o);
                p5 += __shfl_xor_sync(0xffffffffu, p5, o);
                p6 += __shfl_xor_sync(0xffffffffu, p6, o);
                p7 += __shfl_xor_sync(0xffffffffu, p7, o);
            }
            if ((lane & 3) == 0) {
                if (p1 != 0.f) { atomicAdd(&rowAcc[li][0], p0); atomicAdd(&rowAcc[li][1], p1); }
                if (p3 != 0.f) { atomicAdd(&rowAcc[li][2], p2); atomicAdd(&rowAcc[li][3], p3); }
                if (p5 != 0.f) { atomicAdd(&rowAcc[li][4], p4); atomicAdd(&rowAcc[li][5], p5); }
                if (p7 != 0.f) { atomicAdd(&rowAcc[li][6], p6); atomicAdd(&rowAcc[li][7], p7); }
            }
        }
    }

    // ---- Column pass (symmetry credit), off-diagonal only ----
    if (!diag) {
#pragma unroll
        for (int nt = 0; nt < 8; nt++) {
#pragma unroll
            for (int cc = 0; cc < 2; cc++) {
                int lj = warp_n * 64 + nt * 8 + (lane & 3) * 2 + cc;
                int tj = tJ[lj], sj = sJ[lj];
                float p0 = 0.f, p1 = 0.f, p2 = 0.f, p3 = 0.f;
                float p4 = 0.f, p5 = 0.f, p6 = 0.f, p7 = 0.f;
#pragma unroll
                for (int mt = 0; mt < 2; mt++) {
#pragma unroll
                    for (int h = 0; h < 2; h++) {
                        int li = warp_m * 32 + mt * 16 + h * 8 + (lane >> 2);
                        float d = acc[mt][nt][h * 2 + cc];
                        bool same = (tI[li] == tj);
                        bool intra = (sI[li] == sj);
                        if (same) {
                            if (intra) { p0 += fmaxf(d - 1.4f, 0.f); p1 += 1.f; }
                            else       { p2 += fmaxf(d - 0.7f, 0.f); p3 += 1.f; }
                        } else {
                            float alpha = intra ? 2.4f : 2.2f;
                            if (d < alpha) {
                                float diff = alpha - d;
                                float w = __expf(diff);
                                if (intra) { p4 += diff * w; p5 += w; }
                                else       { p6 += diff * w; p7 += w; }
                            }
                        }
                    }
                }
#pragma unroll
                for (int o = 4; o <= 16; o <<= 1) {
                    p0 += __shfl_xor_sync(0xffffffffu, p0, o);
                    p1 += __shfl_xor_sync(0xffffffffu, p1, o);
                    p2 += __shfl_xor_sync(0xffffffffu, p2, o);
                    p3 += __shfl_xor_sync(0xffffffffu, p3, o);
                    p4 += __shfl_xor_sync(0xffffffffu, p4, o);
                    p5 += __shfl_xor_sync(0xffffffffu, p5, o);
                    p6 += __shfl_xor_sync(0xffffffffu, p6, o);
                    p7 += __shfl_xor_sync(0xffffffffu, p7, o);
                }
                if (lane < 4) {
                    if (p1 != 0.f) { atomicAdd(&colAcc[lj][0], p0); atomicAdd(&colAcc[lj][1], p1); }
                    if (p3 != 0.f) { atomicAdd(&colAcc[lj][2], p2); atomicAdd(&colAcc[lj][3], p3); }
                    if (p5 != 0.f) { atomicAdd(&colAcc[lj][4], p4); atomicAdd(&colAcc[lj][5], p5); }
                    if (p7 != 0.f) { atomicAdd(&colAcc[lj][6], p6); atomicAdd(&colAcc[lj][7], p7); }
                }
            }
        }
    }

    __syncthreads();

    for (int i = tid; i < BM * 8; i += 256) {
        int r = i >> 3, s = i & 7;
        float v = ((float*)rowAcc)[i];
        if (v != 0.f) atomicAdd(&g_acc[(bi * BM + r) * 8 + s], v);
        if (!diag) {
            float vc = ((float*)colAcc)[i];
            if (vc != 0.f) atomicAdd(&g_acc[(bj * BN + r) * 8 + s], vc);
        }
    }
}

// ---------------------------------------------------------------------------
// Kernel 3: finalize (1024 threads, strided, better MLP).
// ---------------------------------------------------------------------------
__global__ __launch_bounds__(1024) void finalize_kernel(float* __restrict__ out) {
    int t = threadIdx.x;
    float s = 0.f;
    for (int r = t; r < NROW; r += 1024) {
        const float* a = g_acc + r * 8;
        s += a[0] / (a[1] + EPSF) + a[2] / (a[3] + EPSF)
           + a[4] / (a[5] + EPSF) + a[6] / (a[7] + EPSF);
    }
#pragma unroll
    for (int o = 16; o > 0; o >>= 1) s += __shfl_xor_sync(0xffffffffu, s, o);
    __shared__ float ws[32];
    if ((t & 31) == 0) ws[t >> 5] = s;
    __syncthreads();
    if (t == 0) {
        float tot = 0.f;
#pragma unroll
        for (int i = 0; i < 32; i++) tot += ws[i];
        out[0] = tot / (float)NROW;
    }
}

extern "C" void kernel_launch(void* const* d_in, const int* in_sizes, int n_in,
                              void* d_out, int out_size) {
    const float* x       = (const float*)d_in[0];
    const int*   targets = (const int*)d_in[1];
    const int*   sub     = (const int*)d_in[2];

    int dyn = 1024 + NSTAGE * STAGEB;  // 97.3 KB
    cudaFuncSetAttribute(fused_kernel, cudaFuncAttributeMaxDynamicSharedMemorySize, dyn);

    normalize_kernel<<<NROW, 256>>>(x);
    fused_kernel<<<(NTILE * (NTILE + 1)) / 2, 256, dyn>>>(targets, sub);
    finalize_kernel<<<1, 1024>>>((float*)d_out);
}